// round 4
// baseline (speedup 1.0000x reference)
#include <cuda_runtime.h>
#include <cstdint>
#include <cstddef>

#define BM 128
#define BN 128
#define BK 16
#define SKEW 20   // smem row stride in floats: (r*20 + c) % 32 conflict-free for fragment loads

// Scratch (allocation-free rule: __device__ globals)
static __device__ float g_qkv [(size_t)16384 * 3072];   // 201 MB
static __device__ float g_attn[(size_t)16384 * 1024];   //  67 MB

__device__ __forceinline__ unsigned f2tf(float f) {
    unsigned u;
    asm("cvt.rna.tf32.f32 %0, %1;" : "=r"(u) : "f"(f));
    return u;
}

__device__ __forceinline__ void mma_tf32(float c[4], const unsigned a[4], const unsigned b[2]) {
    asm volatile(
        "mma.sync.aligned.m16n8k8.row.col.f32.tf32.tf32.f32 "
        "{%0,%1,%2,%3}, {%4,%5,%6,%7}, {%8,%9}, {%0,%1,%2,%3};\n"
        : "+f"(c[0]), "+f"(c[1]), "+f"(c[2]), "+f"(c[3])
        : "r"(a[0]), "r"(a[1]), "r"(a[2]), "r"(a[3]), "r"(b[0]), "r"(b[1]));
}

// C[m,n] = sum_k A[m,k] * Bm[n,k]  (+ bias[n]) ; all row-major, K contiguous (NT GEMM)
template <bool HAS_BIAS>
__global__ void __launch_bounds__(256)
gemm_tf32_nt(const float* __restrict__ A, const float* __restrict__ Bm,
             const float* __restrict__ bias, float* __restrict__ C,
             int M, int Nd, int K)
{
    __shared__ unsigned As[2][BM * SKEW];
    __shared__ unsigned Bs[2][BN * SKEW];

    const int tid  = threadIdx.x;
    const int warp = tid >> 5;
    const int lane = tid & 31;
    const int g    = lane >> 2;   // group id 0..7
    const int c    = lane & 3;    // thread-in-group 0..3

    const int bm0 = blockIdx.y * BM;
    const int bn0 = blockIdx.x * BN;

    const int wm = (warp >> 2) * 64;   // warp tile: 64 (M) x 32 (N)
    const int wn = (warp & 3) * 32;

    // global-load mapping: thread loads rows r0 and r0+64, float4 at column q0
    const int r0 = tid >> 2;          // 0..63
    const int q0 = (tid & 3) * 4;     // 0,4,8,12

    const float* Ag0 = A  + (size_t)(bm0 + r0)      * K + q0;
    const float* Ag1 = A  + (size_t)(bm0 + r0 + 64) * K + q0;
    const float* Bg0 = Bm + (size_t)(bn0 + r0)      * K + q0;
    const float* Bg1 = Bm + (size_t)(bn0 + r0 + 64) * K + q0;

    float acc[4][4][4];
    #pragma unroll
    for (int i = 0; i < 4; i++)
        #pragma unroll
        for (int j = 0; j < 4; j++)
            #pragma unroll
            for (int r = 0; r < 4; r++) acc[i][j][r] = 0.f;

    const int sA0 =  r0       * SKEW + q0;
    const int sA1 = (r0 + 64) * SKEW + q0;

    // ---- prologue: load tile 0 into smem buf 0 ----
    {
        float4 a0 = *(const float4*)Ag0;
        float4 a1 = *(const float4*)Ag1;
        float4 b0 = *(const float4*)Bg0;
        float4 b1 = *(const float4*)Bg1;
        *(uint4*)&As[0][sA0] = make_uint4(f2tf(a0.x), f2tf(a0.y), f2tf(a0.z), f2tf(a0.w));
        *(uint4*)&As[0][sA1] = make_uint4(f2tf(a1.x), f2tf(a1.y), f2tf(a1.z), f2tf(a1.w));
        *(uint4*)&Bs[0][sA0] = make_uint4(f2tf(b0.x), f2tf(b0.y), f2tf(b0.z), f2tf(b0.w));
        *(uint4*)&Bs[0][sA1] = make_uint4(f2tf(b1.x), f2tf(b1.y), f2tf(b1.z), f2tf(b1.w));
    }
    __syncthreads();

    const int nIter = K / BK;   // 64
    float4 ra0, ra1, rb0, rb1;

    for (int it = 0; it < nIter; ++it) {
        const int cur = it & 1;
        const int nxt = cur ^ 1;

        if (it + 1 < nIter) {
            const int k1 = (it + 1) * BK;
            ra0 = *(const float4*)(Ag0 + k1);
            ra1 = *(const float4*)(Ag1 + k1);
            rb0 = *(const float4*)(Bg0 + k1);
            rb1 = *(const float4*)(Bg1 + k1);
        }

        const unsigned* __restrict__ Acur = As[cur];
        const unsigned* __restrict__ Bcur = Bs[cur];

        #pragma unroll
        for (int kk = 0; kk < BK; kk += 8) {
            unsigned af[4][4];
            #pragma unroll
            for (int i = 0; i < 4; i++) {
                const int base = (wm + i * 16 + g) * SKEW + kk + c;
                af[i][0] = Acur[base];
                af[i][1] = Acur[base + 8 * SKEW];
                af[i][2] = Acur[base + 4];
                af[i][3] = Acur[base + 8 * SKEW + 4];
            }
            unsigned bf[4][2];
            #pragma unroll
            for (int j = 0; j < 4; j++) {
                const int base = (wn + j * 8 + g) * SKEW + kk + c;
                bf[j][0] = Bcur[base];
                bf[j][1] = Bcur[base + 4];
            }
            #pragma unroll
            for (int i = 0; i < 4; i++)
                #pragma unroll
                for (int j = 0; j < 4; j++)
                    mma_tf32(acc[i][j], af[i], bf[j]);
        }

        if (it + 1 < nIter) {
            *(uint4*)&As[nxt][sA0] = make_uint4(f2tf(ra0.x), f2tf(ra0.y), f2tf(ra0.z), f2tf(ra0.w));
            *(uint4*)&As[nxt][sA1] = make_uint4(f2tf(ra1.x), f2tf(ra1.y), f2tf(ra1.z), f2tf(ra1.w));
            *(uint4*)&Bs[nxt][sA0] = make_uint4(f2tf(rb0.x), f2tf(rb0.y), f2tf(rb0.z), f2tf(rb0.w));
            *(uint4*)&Bs[nxt][sA1] = make_uint4(f2tf(rb1.x), f2tf(rb1.y), f2tf(rb1.z), f2tf(rb1.w));
            __syncthreads();
        }
    }

    // ---- epilogue ----
    #pragma unroll
    for (int i = 0; i < 4; i++) {
        const int row = bm0 + wm + i * 16 + g;
        #pragma unroll
        for (int j = 0; j < 4; j++) {
            const int col = bn0 + wn + j * 8 + c * 2;
            float2 add = make_float2(0.f, 0.f);
            if (HAS_BIAS) add = *(const float2*)(bias + col);
            float2 v0 = make_float2(acc[i][j][0] + add.x, acc[i][j][1] + add.y);
            float2 v1 = make_float2(acc[i][j][2] + add.x, acc[i][j][3] + add.y);
            *(float2*)(C + (size_t)row       * Nd + col) = v0;
            *(float2*)(C + (size_t)(row + 8) * Nd + col) = v1;
        }
    }
}

// Per-position cross-head attention: one block (128 thr) per (b,n) position.
// qkv layout per position: [q(16x64) | k(16x64) | v(16x64)] = 3072 contiguous floats.
__global__ void __launch_bounds__(128)
attn_kernel(const float* __restrict__ qkv, float* __restrict__ attn)
{
    __shared__ float s[3072];
    __shared__ float sS[16 * 17];
    __shared__ float sW[16 * 17];

    const int tid = threadIdx.x;
    const size_t m = blockIdx.x;

    const float4* src = (const float4*)(qkv + m * 3072);
    float4* dst = (float4*)s;
    #pragma unroll
    for (int i = 0; i < 6; i++) dst[tid + i * 128] = src[tid + i * 128];
    __syncthreads();

    const float* q = s;
    const float* k = s + 1024;
    const float* v = s + 2048;

    // scores[h][g] = (q[h]·k[g]) / 32 ; 256 entries, 2 per thread
    #pragma unroll
    for (int e = 0; e < 2; e++) {
        const int idx = tid + e * 128;
        const int h  = idx >> 4;
        const int gg = idx & 15;
        float sum = 0.f;
        #pragma unroll
        for (int d = 0; d < 64; d++) {
            const int dd = (d + gg) & 63;   // rotation kills stride-64 bank conflicts
            sum += q[h * 64 + dd] * k[gg * 64 + dd];
        }
        sS[h * 17 + gg] = sum * 0.03125f;   // 1/sqrt(1024)
    }
    __syncthreads();

    // softmax over g (16 wide), one row per thread
    if (tid < 16) {
        float mx = -1e30f;
        #pragma unroll
        for (int j = 0; j < 16; j++) mx = fmaxf(mx, sS[tid * 17 + j]);
        float w[16], sum = 0.f;
        #pragma unroll
        for (int j = 0; j < 16; j++) { w[j] = __expf(sS[tid * 17 + j] - mx); sum += w[j]; }
        const float inv = 1.f / sum;
        #pragma unroll
        for (int j = 0; j < 16; j++) sW[tid * 17 + j] = w[j] * inv;
    }
    __syncthreads();

    // attn[h][d] = sum_g w[h][g] * v[g][d] ; 8 outputs per thread
    const int h  = tid >> 3;
    const int d0 = (tid & 7) * 8;
    float out[8];
    #pragma unroll
    for (int j = 0; j < 8; j++) out[j] = 0.f;
    #pragma unroll
    for (int gg = 0; gg < 16; gg++) {
        const float w = sW[h * 17 + gg];
        #pragma unroll
        for (int j = 0; j < 8; j++) out[j] += w * v[gg * 64 + d0 + j];
    }
    float4* o4 = (float4*)(attn + m * 1024 + h * 64 + d0);
    o4[0] = make_float4(out[0], out[1], out[2], out[3]);
    o4[1] = make_float4(out[4], out[5], out[6], out[7]);
}

extern "C" void kernel_launch(void* const* d_in, const int* in_sizes, int n_in,
                              void* d_out, int out_size)
{
    const float* x    = (const float*)d_in[0];   // (4,4096,1024)
    const float* Wqkv = (const float*)d_in[1];   // (3072,1024)
    const float* Wo   = (const float*)d_in[2];   // (1024,1024)
    const float* bo   = (const float*)d_in[3];   // (1024)
    float* out = (float*)d_out;

    float *qkv = nullptr, *attn = nullptr;
    cudaGetSymbolAddress((void**)&qkv,  g_qkv);
    cudaGetSymbolAddress((void**)&attn, g_attn);

    const int M = 16384, K = 1024;

    gemm_tf32_nt<false><<<dim3(3072 / BN, M / BM), 256>>>(x,    Wqkv, nullptr, qkv, M, 3072, K);
    attn_kernel<<<M, 128>>>(qkv, attn);
    gemm_tf32_nt<true ><<<dim3(1024 / BN, M / BM), 256>>>(attn, Wo,   bo,      out, M, 1024, K);
}

// round 5
// speedup vs baseline: 1.0014x; 1.0014x over previous
#include <cuda_runtime.h>
#include <cstdint>
#include <cstddef>

#define BM 128
#define BN 128
#define BK 16
#define SKEW 20   // smem row stride in floats: (r*20 + c) % 32 conflict-free for fragment loads

// Scratch (allocation-free rule: __device__ globals)
static __device__ float g_qkv [(size_t)16384 * 3072];   // 201 MB
static __device__ float g_attn[(size_t)16384 * 1024];   //  67 MB

__device__ __forceinline__ unsigned f2tf(float f) {
    unsigned u;
    asm("cvt.rna.tf32.f32 %0, %1;" : "=r"(u) : "f"(f));
    return u;
}

__device__ __forceinline__ void mma_tf32(float c[4], const unsigned a[4], const unsigned b[2]) {
    asm volatile(
        "mma.sync.aligned.m16n8k8.row.col.f32.tf32.tf32.f32 "
        "{%0,%1,%2,%3}, {%4,%5,%6,%7}, {%8,%9}, {%0,%1,%2,%3};\n"
        : "+f"(c[0]), "+f"(c[1]), "+f"(c[2]), "+f"(c[3])
        : "r"(a[0]), "r"(a[1]), "r"(a[2]), "r"(a[3]), "r"(b[0]), "r"(b[1]));
}

// C[m,n] = sum_k A[m,k] * Bm[n,k]  (+ bias[n]) ; all row-major, K contiguous (NT GEMM)
template <bool HAS_BIAS>
__global__ void __launch_bounds__(256)
gemm_tf32_nt(const float* __restrict__ A, const float* __restrict__ Bm,
             const float* __restrict__ bias, float* __restrict__ C,
             int M, int Nd, int K)
{
    __shared__ unsigned As[2][BM * SKEW];
    __shared__ unsigned Bs[2][BN * SKEW];

    const int tid  = threadIdx.x;
    const int warp = tid >> 5;
    const int lane = tid & 31;
    const int g    = lane >> 2;   // group id 0..7
    const int c    = lane & 3;    // thread-in-group 0..3

    const int bm0 = blockIdx.y * BM;
    const int bn0 = blockIdx.x * BN;

    const int wm = (warp >> 2) * 64;   // warp tile: 64 (M) x 32 (N)
    const int wn = (warp & 3) * 32;

    // global-load mapping: thread loads rows r0 and r0+64, float4 at column q0
    const int r0 = tid >> 2;          // 0..63
    const int q0 = (tid & 3) * 4;     // 0,4,8,12

    const float* Ag0 = A  + (size_t)(bm0 + r0)      * K + q0;
    const float* Ag1 = A  + (size_t)(bm0 + r0 + 64) * K + q0;
    const float* Bg0 = Bm + (size_t)(bn0 + r0)      * K + q0;
    const float* Bg1 = Bm + (size_t)(bn0 + r0 + 64) * K + q0;

    float acc[4][4][4];
    #pragma unroll
    for (int i = 0; i < 4; i++)
        #pragma unroll
        for (int j = 0; j < 4; j++)
            #pragma unroll
            for (int r = 0; r < 4; r++) acc[i][j][r] = 0.f;

    const int sA0 =  r0       * SKEW + q0;
    const int sA1 = (r0 + 64) * SKEW + q0;

    // ---- prologue: load tile 0 into smem buf 0 ----
    {
        float4 a0 = *(const float4*)Ag0;
        float4 a1 = *(const float4*)Ag1;
        float4 b0 = *(const float4*)Bg0;
        float4 b1 = *(const float4*)Bg1;
        *(uint4*)&As[0][sA0] = make_uint4(f2tf(a0.x), f2tf(a0.y), f2tf(a0.z), f2tf(a0.w));
        *(uint4*)&As[0][sA1] = make_uint4(f2tf(a1.x), f2tf(a1.y), f2tf(a1.z), f2tf(a1.w));
        *(uint4*)&Bs[0][sA0] = make_uint4(f2tf(b0.x), f2tf(b0.y), f2tf(b0.z), f2tf(b0.w));
        *(uint4*)&Bs[0][sA1] = make_uint4(f2tf(b1.x), f2tf(b1.y), f2tf(b1.z), f2tf(b1.w));
    }
    __syncthreads();

    const int nIter = K / BK;   // 64
    float4 ra0, ra1, rb0, rb1;

    for (int it = 0; it < nIter; ++it) {
        const int cur = it & 1;
        const int nxt = cur ^ 1;

        if (it + 1 < nIter) {
            const int k1 = (it + 1) * BK;
            ra0 = *(const float4*)(Ag0 + k1);
            ra1 = *(const float4*)(Ag1 + k1);
            rb0 = *(const float4*)(Bg0 + k1);
            rb1 = *(const float4*)(Bg1 + k1);
        }

        const unsigned* __restrict__ Acur = As[cur];
        const unsigned* __restrict__ Bcur = Bs[cur];

        #pragma unroll
        for (int kk = 0; kk < BK; kk += 8) {
            unsigned af[4][4];
            #pragma unroll
            for (int i = 0; i < 4; i++) {
                const int base = (wm + i * 16 + g) * SKEW + kk + c;
                af[i][0] = Acur[base];
                af[i][1] = Acur[base + 8 * SKEW];
                af[i][2] = Acur[base + 4];
                af[i][3] = Acur[base + 8 * SKEW + 4];
            }
            unsigned bf[4][2];
            #pragma unroll
            for (int j = 0; j < 4; j++) {
                const int base = (wn + j * 8 + g) * SKEW + kk + c;
                bf[j][0] = Bcur[base];
                bf[j][1] = Bcur[base + 4];
            }
            #pragma unroll
            for (int i = 0; i < 4; i++)
                #pragma unroll
                for (int j = 0; j < 4; j++)
                    mma_tf32(acc[i][j], af[i], bf[j]);
        }

        if (it + 1 < nIter) {
            *(uint4*)&As[nxt][sA0] = make_uint4(f2tf(ra0.x), f2tf(ra0.y), f2tf(ra0.z), f2tf(ra0.w));
            *(uint4*)&As[nxt][sA1] = make_uint4(f2tf(ra1.x), f2tf(ra1.y), f2tf(ra1.z), f2tf(ra1.w));
            *(uint4*)&Bs[nxt][sA0] = make_uint4(f2tf(rb0.x), f2tf(rb0.y), f2tf(rb0.z), f2tf(rb0.w));
            *(uint4*)&Bs[nxt][sA1] = make_uint4(f2tf(rb1.x), f2tf(rb1.y), f2tf(rb1.z), f2tf(rb1.w));
            __syncthreads();
        }
    }

    // ---- epilogue ----
    #pragma unroll
    for (int i = 0; i < 4; i++) {
        const int row = bm0 + wm + i * 16 + g;
        #pragma unroll
        for (int j = 0; j < 4; j++) {
            const int col = bn0 + wn + j * 8 + c * 2;
            float2 add = make_float2(0.f, 0.f);
            if (HAS_BIAS) add = *(const float2*)(bias + col);
            float2 v0 = make_float2(acc[i][j][0] + add.x, acc[i][j][1] + add.y);
            float2 v1 = make_float2(acc[i][j][2] + add.x, acc[i][j][3] + add.y);
            *(float2*)(C + (size_t)row       * Nd + col) = v0;
            *(float2*)(C + (size_t)(row + 8) * Nd + col) = v1;
        }
    }
}

// Per-position cross-head attention: one block (128 thr) per (b,n) position.
// qkv layout per position: [q(16x64) | k(16x64) | v(16x64)] = 3072 contiguous floats.
__global__ void __launch_bounds__(128)
attn_kernel(const float* __restrict__ qkv, float* __restrict__ attn)
{
    __shared__ float s[3072];
    __shared__ float sS[16 * 17];
    __shared__ float sW[16 * 17];

    const int tid = threadIdx.x;
    const size_t m = blockIdx.x;

    const float4* src = (const float4*)(qkv + m * 3072);
    float4* dst = (float4*)s;
    #pragma unroll
    for (int i = 0; i < 6; i++) dst[tid + i * 128] = src[tid + i * 128];
    __syncthreads();

    const float* q = s;
    const float* k = s + 1024;
    const float* v = s + 2048;

    // scores[h][g] = (q[h]·k[g]) / 32 ; 256 entries, 2 per thread
    #pragma unroll
    for (int e = 0; e < 2; e++) {
        const int idx = tid + e * 128;
        const int h  = idx >> 4;
        const int gg = idx & 15;
        float sum = 0.f;
        #pragma unroll
        for (int d = 0; d < 64; d++) {
            const int dd = (d + gg) & 63;   // rotation kills stride-64 bank conflicts
            sum += q[h * 64 + dd] * k[gg * 64 + dd];
        }
        sS[h * 17 + gg] = sum * 0.03125f;   // 1/sqrt(1024)
    }
    __syncthreads();

    // softmax over g (16 wide), one row per thread
    if (tid < 16) {
        float mx = -1e30f;
        #pragma unroll
        for (int j = 0; j < 16; j++) mx = fmaxf(mx, sS[tid * 17 + j]);
        float w[16], sum = 0.f;
        #pragma unroll
        for (int j = 0; j < 16; j++) { w[j] = __expf(sS[tid * 17 + j] - mx); sum += w[j]; }
        const float inv = 1.f / sum;
        #pragma unroll
        for (int j = 0; j < 16; j++) sW[tid * 17 + j] = w[j] * inv;
    }
    __syncthreads();

    // attn[h][d] = sum_g w[h][g] * v[g][d] ; 8 outputs per thread
    const int h  = tid >> 3;
    const int d0 = (tid & 7) * 8;
    float out[8];
    #pragma unroll
    for (int j = 0; j < 8; j++) out[j] = 0.f;
    #pragma unroll
    for (int gg = 0; gg < 16; gg++) {
        const float w = sW[h * 17 + gg];
        #pragma unroll
        for (int j = 0; j < 8; j++) out[j] += w * v[gg * 64 + d0 + j];
    }
    float4* o4 = (float4*)(attn + m * 1024 + h * 64 + d0);
    o4[0] = make_float4(out[0], out[1], out[2], out[3]);
    o4[1] = make_float4(out[4], out[5], out[6], out[7]);
}

extern "C" void kernel_launch(void* const* d_in, const int* in_sizes, int n_in,
                              void* d_out, int out_size)
{
    const float* x    = (const float*)d_in[0];   // (4,4096,1024)
    const float* Wqkv = (const float*)d_in[1];   // (3072,1024)
    const float* Wo   = (const float*)d_in[2];   // (1024,1024)
    const float* bo   = (const float*)d_in[3];   // (1024)
    float* out = (float*)d_out;

    float *qkv = nullptr, *attn = nullptr;
    cudaGetSymbolAddress((void**)&qkv,  g_qkv);
    cudaGetSymbolAddress((void**)&attn, g_attn);

    const int M = 16384, K = 1024;

    gemm_tf32_nt<false><<<dim3(3072 / BN, M / BM), 256>>>(x,    Wqkv, nullptr, qkv, M, 3072, K);
    attn_kernel<<<M, 128>>>(qkv, attn);
    gemm_tf32_nt<true ><<<dim3(1024 / BN, M / BM), 256>>>(attn, Wo,   bo,      out, M, 1024, K);
}